// round 3
// baseline (speedup 1.0000x reference)
#include <cuda_runtime.h>
#include <stdint.h>

// Problem constants: N=200000 nodes, D=64, E=4000000 edges, 3 layers.
#define MAX_N 200000
#define DIM   64
#define MAX_E 4000000
#define SCAN_BLK 256
#define MAX_NBLK 1024   // supports N up to 256*1024

// Scratch (__device__ globals — allocation-free rule).
__device__ int g_is64;                              // 1 if edge_index buffer is int64
__device__ __align__(128) int   g_deg[MAX_N];       // in-degree (int histogram)
__device__ __align__(128) float g_dinv[MAX_N];      // deg^{-1/2} per reference
__device__ __align__(128) int   g_rowptr[MAX_N];    // CSR bucket starts (exclusive scan)
__device__ __align__(128) int   g_cursor[MAX_N];    // atomic fill cursors
__device__ __align__(128) int   g_partial[MAX_NBLK];
__device__ __align__(128) int   g_csrc[MAX_E];      // CSR: source node per slot
__device__ __align__(128) int   g_esrc[MAX_E];      // decoded src per edge
__device__ __align__(128) int   g_edst[MAX_E];      // decoded dst per edge
__device__ __align__(128) float g_cw[MAX_E];        // CSR: edge weight per slot
__device__ __align__(128) float g_e1[(size_t)MAX_N * DIM];
__device__ __align__(128) float g_e2[(size_t)MAX_N * DIM];
__device__ __align__(128) float g_e3[(size_t)MAX_N * DIM];

// ------------------------------------------------ dtype probe + zero degree
// If buffer is int64 (values < 2^31), every odd int32 word is 0. For int32
// data with values uniform in [0,200000), 32 consecutive zeros is impossible.
__global__ void probe_kernel(const int* __restrict__ ei32) {
    if (blockIdx.x == 0 && threadIdx.x == 0) {
        int all_zero = 1;
        for (int i = 0; i < 32; i++)
            if (ei32[2 * i + 1] != 0) { all_zero = 0; break; }
        g_is64 = all_zero;
    }
}

__global__ void zero_deg_kernel(int N) {
    int i = blockIdx.x * blockDim.x + threadIdx.x;
    if (i < N) g_deg[i] = 0;
}

// --------------------------- edge decode (either dtype) + degree histogram
__global__ void build_edges_kernel(const int* __restrict__ ei32, int E, int N) {
    int e = blockIdx.x * blockDim.x + threadIdx.x;
    if (e >= E) return;
    int s, d;
    if (g_is64) {                 // int64 little-endian: take low words
        s = ei32[2 * (size_t)e];
        d = ei32[2 * ((size_t)E + e)];
    } else {                      // int32
        s = ei32[e];
        d = ei32[(size_t)E + e];
    }
    // clamp: turn any surprise into wrong-answer, not a trap
    s = min(max(s, 0), N - 1);
    d = min(max(d, 0), N - 1);
    g_esrc[e] = s;
    g_edst[e] = d;
    atomicAdd(&g_deg[d], 1);
}

// -------------------------------------------------------------------- dinv
__global__ void dinv_kernel(int N) {
    int i = blockIdx.x * blockDim.x + threadIdx.x;
    if (i >= N) return;
    int dg = g_deg[i];
    g_dinv[i] = (dg > 0) ? rsqrtf((float)dg) : 0.f;   // deg>=1 so max(deg,1)==deg
}

// --------------------------------------------------- scan pass 1: block sums
__global__ void scan1_kernel(int N) {
    __shared__ int sh[SCAN_BLK];
    int tid = threadIdx.x;
    int i = blockIdx.x * SCAN_BLK + tid;
    sh[tid] = (i < N) ? g_deg[i] : 0;
    __syncthreads();
    for (int s = SCAN_BLK / 2; s > 0; s >>= 1) {
        if (tid < s) sh[tid] += sh[tid + s];
        __syncthreads();
    }
    if (tid == 0) g_partial[blockIdx.x] = sh[0];
}

// ------------------------------- scan pass 2: exclusive scan of block sums
__global__ void scan2_kernel(int nblk) {
    __shared__ int sh[MAX_NBLK];
    int tid = threadIdx.x;                 // launched with MAX_NBLK threads
    int v = (tid < nblk) ? g_partial[tid] : 0;
    sh[tid] = v;
    __syncthreads();
    for (int off = 1; off < MAX_NBLK; off <<= 1) {
        int t = (tid >= off) ? sh[tid - off] : 0;
        __syncthreads();
        sh[tid] += t;
        __syncthreads();
    }
    if (tid < nblk) g_partial[tid] = sh[tid] - v;  // inclusive -> exclusive
}

// ------------------- scan pass 3: per-block exclusive scan + offset -> rowptr
__global__ void scan3_kernel(int N) {
    __shared__ int sh[SCAN_BLK];
    int tid = threadIdx.x;
    int i = blockIdx.x * SCAN_BLK + tid;
    int v = (i < N) ? g_deg[i] : 0;
    sh[tid] = v;
    __syncthreads();
    for (int off = 1; off < SCAN_BLK; off <<= 1) {
        int t = (tid >= off) ? sh[tid - off] : 0;
        __syncthreads();
        sh[tid] += t;
        __syncthreads();
    }
    if (i < N) {
        int excl = sh[tid] - v + g_partial[blockIdx.x];
        g_rowptr[i] = excl;
        g_cursor[i] = excl;
    }
}

// ----------------------------------------- CSR fill: (src, weight) by bucket
__global__ void fill_kernel(int E) {
    int e = blockIdx.x * blockDim.x + threadIdx.x;
    if (e >= E) return;
    int s = g_esrc[e];
    int d = g_edst[e];
    float w = __ldg(&g_dinv[s]) * __ldg(&g_dinv[d]);
    int pos = atomicAdd(&g_cursor[d], 1);
    g_csrc[pos] = s;
    g_cw[pos] = w;
}

// ------------------------- propagation layer: pure gather, one warp per node
// out[d] = sum over incoming edges of w * in[src]; each lane owns a float2.
__global__ void layer_kernel(int layer, const float* __restrict__ emb0, int N) {
    int warp = (blockIdx.x * blockDim.x + threadIdx.x) >> 5;
    int lane = threadIdx.x & 31;
    if (warp >= N) return;

    const float* in  = (layer == 0) ? emb0 : (layer == 1) ? g_e1 : g_e2;
    float*       out = (layer == 0) ? g_e1 : (layer == 1) ? g_e2 : g_e3;

    int beg = __ldg(&g_rowptr[warp]);
    int cnt = __ldg(&g_deg[warp]);

    const float2* inp = reinterpret_cast<const float2*>(in);
    float2 acc = make_float2(0.f, 0.f);

    #pragma unroll 4
    for (int i = 0; i < cnt; i++) {
        int   s = __ldg(&g_csrc[beg + i]);      // warp-broadcast
        float w = __ldg(&g_cw[beg + i]);        // warp-broadcast
        float2 v = __ldg(&inp[(size_t)s * 32 + lane]);  // coalesced 256B row
        acc.x += w * v.x;
        acc.y += w * v.y;
    }
    reinterpret_cast<float2*>(out)[(size_t)warp * 32 + lane] = acc;
}

// --------------- finalize: out[0:nd)=emb0 ; out[nd:2nd)=(e0+e1+e2+e3)/4
__global__ void finalize_kernel(const float* __restrict__ emb0, float* __restrict__ out,
                                long long nd4) {
    long long i = (long long)blockIdx.x * blockDim.x + threadIdx.x;
    long long stride = (long long)gridDim.x * blockDim.x;
    const float4* e0 = reinterpret_cast<const float4*>(emb0);
    const float4* e1 = reinterpret_cast<const float4*>(g_e1);
    const float4* e2 = reinterpret_cast<const float4*>(g_e2);
    const float4* e3 = reinterpret_cast<const float4*>(g_e3);
    float4* o0 = reinterpret_cast<float4*>(out);
    float4* o1 = o0 + nd4;
    for (long long j = i; j < nd4; j += stride) {
        float4 a = e0[j], b = e1[j], c = e2[j], d = e3[j];
        o0[j] = a;
        float4 r;
        r.x = 0.25f * (a.x + b.x + c.x + d.x);
        r.y = 0.25f * (a.y + b.y + c.y + d.y);
        r.z = 0.25f * (a.z + b.z + c.z + d.z);
        r.w = 0.25f * (a.w + b.w + c.w + d.w);
        o1[j] = r;
    }
}

extern "C" void kernel_launch(void* const* d_in, const int* in_sizes, int n_in,
                              void* d_out, int out_size) {
    const int*   ei32 = (const int*)d_in[0];     // edge_index [2, E] (int32 or int64)
    const float* emb  = (const float*)d_in[1];   // emb_weight [N, D] float32
    int       E   = in_sizes[0] / 2;
    long long nd  = (long long)in_sizes[1];
    int       N   = (int)(nd / DIM);
    long long nd4 = nd / 4;
    float* out = (float*)d_out;

    int nblk = (N + SCAN_BLK - 1) / SCAN_BLK;

    probe_kernel<<<1, 32>>>(ei32);
    zero_deg_kernel<<<(N + 255) / 256, 256>>>(N);
    build_edges_kernel<<<(E + 255) / 256, 256>>>(ei32, E, N);
    dinv_kernel<<<(N + 255) / 256, 256>>>(N);
    scan1_kernel<<<nblk, SCAN_BLK>>>(N);
    scan2_kernel<<<1, MAX_NBLK>>>(nblk);
    scan3_kernel<<<nblk, SCAN_BLK>>>(N);
    fill_kernel<<<(E + 255) / 256, 256>>>(E);

    int lblocks = (N * 32 + 255) / 256;   // one warp per node, 8 warps/block
    layer_kernel<<<lblocks, 256>>>(0, emb, N);
    layer_kernel<<<lblocks, 256>>>(1, emb, N);
    layer_kernel<<<lblocks, 256>>>(2, emb, N);

    finalize_kernel<<<2048, 256>>>(emb, out, nd4);
}

// round 5
// speedup vs baseline: 1.2464x; 1.2464x over previous
#include <cuda_runtime.h>
#include <cuda_fp16.h>
#include <stdint.h>

// Problem constants: N=200000 nodes, D=64, E=4000000 edges, 3 layers.
#define MAX_N 200000
#define DIM   64
#define MAX_E 4000000
#define SCAN_BLK 256
#define MAX_NBLK 1024   // supports N up to 256*1024

// Scratch (__device__ globals — allocation-free rule).
// NOTE: these symbols are ONLY referenced from device code (never passed as
// host-side kernel args — host shadow addresses are silently wrong on ATS).
__device__ int g_is64;                              // 1 if edge_index buffer is int64
__device__ __align__(128) int    g_deg[MAX_N];      // in-degree histogram
__device__ __align__(128) float  g_dinv[MAX_N];     // deg^{-1/2}
__device__ __align__(128) float  g_dinv2[MAX_N];    // deg^{-1}
__device__ __align__(128) float  g_rdeg[MAX_N];     // sqrt(deg) (0 if deg==0)
__device__ __align__(128) int    g_rowptr[MAX_N];   // CSR bucket starts
__device__ __align__(128) int    g_cursor[MAX_N];   // atomic fill cursors
__device__ __align__(128) int    g_partial[MAX_NBLK];
__device__ __align__(128) int    g_csrc[MAX_E];     // CSR: source node per slot
__device__ __align__(128) int    g_esrc[MAX_E];     // decoded src per edge
__device__ __align__(128) int    g_edst[MAX_E];     // decoded dst per edge
// Propagated state y_k = dinv .* e_k, fp16 storage (fp32 accumulation).
__device__ __align__(128) __half g_y0[(size_t)MAX_N * DIM];
__device__ __align__(128) __half g_y1[(size_t)MAX_N * DIM];
__device__ __align__(128) __half g_y2[(size_t)MAX_N * DIM];

// ------------------------------------------------ dtype probe
// int64 little-endian with values < 2^31 -> every odd int32 word is 0.
__global__ void probe_kernel(const int* __restrict__ ei32) {
    if (blockIdx.x == 0 && threadIdx.x == 0) {
        int all_zero = 1;
        for (int i = 0; i < 32; i++)
            if (ei32[2 * i + 1] != 0) { all_zero = 0; break; }
        g_is64 = all_zero;
    }
}

__global__ void zero_deg_kernel(int N) {
    int i = blockIdx.x * blockDim.x + threadIdx.x;
    if (i < N) g_deg[i] = 0;
}

// --------------------------- edge decode (either dtype) + degree histogram
__global__ void build_edges_kernel(const int* __restrict__ ei32, int E, int N) {
    int e = blockIdx.x * blockDim.x + threadIdx.x;
    if (e >= E) return;
    int s, d;
    if (g_is64) {
        s = ei32[2 * (size_t)e];
        d = ei32[2 * ((size_t)E + e)];
    } else {
        s = ei32[e];
        d = ei32[(size_t)E + e];
    }
    s = min(max(s, 0), N - 1);
    d = min(max(d, 0), N - 1);
    g_esrc[e] = s;
    g_edst[e] = d;
    atomicAdd(&g_deg[d], 1);
}

// ----------------- dinv / dinv^2 / sqrt(deg)  (deg>=1 => max(deg,1)==deg)
__global__ void dinv_kernel(int N) {
    int i = blockIdx.x * blockDim.x + threadIdx.x;
    if (i >= N) return;
    int dg = g_deg[i];
    float di = (dg > 0) ? rsqrtf((float)dg) : 0.f;
    g_dinv[i]  = di;
    g_dinv2[i] = di * di;
    g_rdeg[i]  = (dg > 0) ? sqrtf((float)dg) : 0.f;
}

// ------------------------------- y0 = dinv .* emb0, cast to fp16
__global__ void y0_kernel(const float* __restrict__ emb0, int N) {
    int t = blockIdx.x * blockDim.x + threadIdx.x;   // one thread per float2 chunk
    if (t >= N * 32) return;
    int node = t >> 5;
    float w = __ldg(&g_dinv[node]);
    float2 v = __ldg(reinterpret_cast<const float2*>(emb0) + t);
    reinterpret_cast<half2*>(g_y0)[t] = __floats2half2_rn(w * v.x, w * v.y);
}

// --------------------------------------------------- scan pass 1: block sums
__global__ void scan1_kernel(int N) {
    __shared__ int sh[SCAN_BLK];
    int tid = threadIdx.x;
    int i = blockIdx.x * SCAN_BLK + tid;
    sh[tid] = (i < N) ? g_deg[i] : 0;
    __syncthreads();
    for (int s = SCAN_BLK / 2; s > 0; s >>= 1) {
        if (tid < s) sh[tid] += sh[tid + s];
        __syncthreads();
    }
    if (tid == 0) g_partial[blockIdx.x] = sh[0];
}

// ------------------------------- scan pass 2: exclusive scan of block sums
__global__ void scan2_kernel(int nblk) {
    __shared__ int sh[MAX_NBLK];
    int tid = threadIdx.x;
    int v = (tid < nblk) ? g_partial[tid] : 0;
    sh[tid] = v;
    __syncthreads();
    for (int off = 1; off < MAX_NBLK; off <<= 1) {
        int t = (tid >= off) ? sh[tid - off] : 0;
        __syncthreads();
        sh[tid] += t;
        __syncthreads();
    }
    if (tid < nblk) g_partial[tid] = sh[tid] - v;
}

// ------------------- scan pass 3: per-block exclusive scan + offset -> rowptr
__global__ void scan3_kernel(int N) {
    __shared__ int sh[SCAN_BLK];
    int tid = threadIdx.x;
    int i = blockIdx.x * SCAN_BLK + tid;
    int v = (i < N) ? g_deg[i] : 0;
    sh[tid] = v;
    __syncthreads();
    for (int off = 1; off < SCAN_BLK; off <<= 1) {
        int t = (tid >= off) ? sh[tid - off] : 0;
        __syncthreads();
        sh[tid] += t;
        __syncthreads();
    }
    if (i < N) {
        int excl = sh[tid] - v + g_partial[blockIdx.x];
        g_rowptr[i] = excl;
        g_cursor[i] = excl;
    }
}

// ----------------------------------------- CSR fill: src only (no weights!)
__global__ void fill_kernel(int E) {
    int e = blockIdx.x * blockDim.x + threadIdx.x;
    if (e >= E) return;
    int d = g_edst[e];
    int pos = atomicAdd(&g_cursor[d], 1);
    g_csrc[pos] = g_esrc[e];
}

// ---------------- propagation layer: y_out[d] = dinv2[d] * sum y_in[src]
// One warp per node; lane owns one half2 (4B) of the 128B fp16 row.
// Buffer selection happens in DEVICE code via layer index.
__global__ void layer_kernel(int layer, int N) {
    int warp = (blockIdx.x * blockDim.x + threadIdx.x) >> 5;
    int lane = threadIdx.x & 31;
    if (warp >= N) return;

    const half2* inp  = reinterpret_cast<const half2*>((layer == 0) ? g_y0 : g_y1);
    half2*       outp = reinterpret_cast<half2*>((layer == 0) ? g_y1 : g_y2);

    int beg = __ldg(&g_rowptr[warp]);
    int cnt = __ldg(&g_deg[warp]);

    float2 acc = make_float2(0.f, 0.f);
    #pragma unroll 4
    for (int i = 0; i < cnt; i++) {
        int s = __ldg(&g_csrc[beg + i]);                          // warp-broadcast
        float2 v = __half22float2(__ldg(&inp[(size_t)s * 32 + lane]));  // 128B row
        acc.x += v.x;
        acc.y += v.y;
    }
    float w = __ldg(&g_dinv2[warp]);
    outp[(size_t)warp * 32 + lane] = __floats2half2_rn(w * acc.x, w * acc.y);
}

// ------- fused last layer + finalize:
// y3[d] = dinv2[d] * sum y2[src]   (never stored)
// out[0:nd)  = emb0
// out[nd:2nd)= (e0 + sqrt(deg[d])*(y1+y2+y3)) / 4
__global__ void layer3_finalize_kernel(const float* __restrict__ emb0,
                                       float* __restrict__ out, int N, long long nd2) {
    int warp = (blockIdx.x * blockDim.x + threadIdx.x) >> 5;
    int lane = threadIdx.x & 31;
    if (warp >= N) return;

    int beg = __ldg(&g_rowptr[warp]);
    int cnt = __ldg(&g_deg[warp]);
    const half2* y2p = reinterpret_cast<const half2*>(g_y2);

    float2 acc = make_float2(0.f, 0.f);
    #pragma unroll 4
    for (int i = 0; i < cnt; i++) {
        int s = __ldg(&g_csrc[beg + i]);
        float2 v = __half22float2(__ldg(&y2p[(size_t)s * 32 + lane]));
        acc.x += v.x;
        acc.y += v.y;
    }
    float w2 = __ldg(&g_dinv2[warp]);
    float rd = __ldg(&g_rdeg[warp]);
    long long idx = (long long)warp * 32 + lane;

    float2 e0 = __ldg(reinterpret_cast<const float2*>(emb0) + idx);
    float2 h1 = __half22float2(__ldg(reinterpret_cast<const half2*>(g_y1) + idx));
    float2 h2 = __half22float2(__ldg(y2p + idx));

    float2 r;
    r.x = 0.25f * (e0.x + rd * (h1.x + h2.x + w2 * acc.x));
    r.y = 0.25f * (e0.y + rd * (h1.y + h2.y + w2 * acc.y));

    float2* o = reinterpret_cast<float2*>(out);
    o[idx] = e0;            // exact fp32 copy of emb0
    o[nd2 + idx] = r;       // mean embedding
}

extern "C" void kernel_launch(void* const* d_in, const int* in_sizes, int n_in,
                              void* d_out, int out_size) {
    const int*   ei32 = (const int*)d_in[0];     // edge_index [2, E] (int32 or int64)
    const float* emb  = (const float*)d_in[1];   // emb_weight [N, D] float32
    int       E   = in_sizes[0] / 2;
    long long nd  = (long long)in_sizes[1];
    int       N   = (int)(nd / DIM);
    long long nd2 = nd / 2;                      // number of float2 chunks
    float* out = (float*)d_out;

    int nblk = (N + SCAN_BLK - 1) / SCAN_BLK;
    int eblk = (E + 255) / 256;
    int wblk = (N * 32 + 255) / 256;             // one warp per node

    probe_kernel<<<1, 32>>>(ei32);
    zero_deg_kernel<<<(N + 255) / 256, 256>>>(N);
    build_edges_kernel<<<eblk, 256>>>(ei32, E, N);
    dinv_kernel<<<(N + 255) / 256, 256>>>(N);
    y0_kernel<<<wblk, 256>>>(emb, N);
    scan1_kernel<<<nblk, SCAN_BLK>>>(N);
    scan2_kernel<<<1, MAX_NBLK>>>(nblk);
    scan3_kernel<<<nblk, SCAN_BLK>>>(N);
    fill_kernel<<<eblk, 256>>>(E);

    layer_kernel<<<wblk, 256>>>(0, N);
    layer_kernel<<<wblk, 256>>>(1, N);
    layer3_finalize_kernel<<<wblk, 256>>>(emb, out, N, nd2);
}